// round 10
// baseline (speedup 1.0000x reference)
#include <cuda_runtime.h>
#include <cfloat>

#define BB    4
#define NN    16384
#define MM    1024
#define CC    64
#define COP   64
#define COUT  128
#define KK    32
#define R2    0.25f
#define XS    84        // s_X row stride (floats); 21 16B-blocks: 16 feat + rel
#define WPC   4         // warps (= centers) per CTA

typedef unsigned long long ull;

// In-place packed dual-FMA: d.{lo,hi} += x.{lo,hi} * w.{lo,hi}
__device__ __forceinline__ void ffma2p(ull& d, ull x, ull w) {
    asm("fma.rn.f32x2 %0, %1, %2, %0;" : "+l"(d) : "l"(x), "l"(w));
}
__device__ __forceinline__ ull dupf(float w) {
    ull r;
    asm("mov.b64 %0, {%1, %1};" : "=l"(r) : "f"(w));
    return r;
}

__global__ __launch_bounds__(128, 4)
void pointnet_sampler_kernel(
    const float* __restrict__ positions,   // (B, N, 3)
    const float* __restrict__ features,    // (B, N, 64)
    const float* __restrict__ centers,     // (B, M, 3)
    const float* __restrict__ distances,   // (B, M, N)
    const float* __restrict__ W_op,        // (67, 64): rows 0..2 rel, 3..66 feat
    const float* __restrict__ b_op,        // (64)
    const float* __restrict__ W_agg,       // (64, 128)
    const float* __restrict__ b_agg,       // (128)
    float* __restrict__ out)               // (B, M, 128)
{
    const int tid  = threadIdx.x;
    const int lane = tid & 31;
    const int wid  = tid >> 5;
    const int gw   = blockIdx.x * WPC + wid;   // global center index
    const int b    = gw >> 10;
    const int m    = gw & (MM - 1);
    const int ktg  = lane >> 3;                // k-tile: k in [8ktg, 8ktg+8)
    const int ct   = lane & 7;                 // c-tile: c in [8ct, 8ct+8)

    // k-major X: row k holds feature block ib at physical block ib^(k>>3)
    // (16B blocks at float cols 4*pb, pb=0..15); rel xyz at cols 64+4*(k>>3).
    __shared__ __align__(16) float s_X[WPC][KK][XS];
    __shared__ int   s_idx[WPC][KK];
    __shared__ float s_pool[COP][6];   // [cc][g0 g1 g2 g3 pad pad]

    // ---- Phase A: ball query (warp-local), R8-style ballot scan ----
    const float* drow = distances + ((size_t)b * MM + m) * NN;
    float dv[8];
#pragma unroll
    for (int j = 0; j < 8; j++) dv[j] = drow[j * 32 + lane];

    int count = 0;
#pragma unroll
    for (int j = 0; j < 8; j++) {
        if (count < KK) {                      // warp-uniform
            bool v = dv[j] < R2;
            unsigned msk = __ballot_sync(0xffffffffu, v);
            int pre = __popc(msk & ((1u << lane) - 1u));
            if (v && count + pre < KK) s_idx[wid][count + pre] = j * 32 + lane;
            count += __popc(msk);
        }
    }
    int base = 256;
    while (count < KK && base < NN) {          // rare fallback (~1% of rows)
        float d = drow[base + lane];
        bool v = d < R2;
        unsigned msk = __ballot_sync(0xffffffffu, v);
        int pre = __popc(msk & ((1u << lane) - 1u));
        if (v && count + pre < KK) s_idx[wid][count + pre] = base + lane;
        count += __popc(msk);
        base += 32;
    }
    const int V = min(count, KK);              // warp-uniform
    __syncwarp();

    // ---- rel-pos: lane = k, stored at swizzle-safe col 64 + 4*(k>>3) ----
    if (lane < V) {
        const float* cp = centers   + ((size_t)b * MM + m) * 3;
        const float* pp = positions + ((size_t)b * NN + s_idx[wid][lane]) * 3;
        float* r = &s_X[wid][lane][64 + 4 * (lane >> 3)];
        r[0] = pp[0] - cp[0];
        r[1] = pp[1] - cp[1];
        r[2] = pp[2] - cp[2];
    }

    // ---- feature gather: coalesced LDG.128 -> swizzled STS.128 (k-major) ----
    {
        const float* featb = features + (size_t)b * NN * CC;
        const int c16 = lane & 15;             // logical 16B block (4 i's)
        const int khalf = lane >> 4;
#pragma unroll
        for (int jb = 0; jb < 4; jb++) {
            float4 v[4];
            int kk[4];
#pragma unroll
            for (int jj = 0; jj < 4; jj++) {
                int j = 4 * jb + jj;
                int k = 2 * j + khalf;
                kk[jj] = k;
                int id = (k < V) ? s_idx[wid][k] : 0;
                v[jj] = *reinterpret_cast<const float4*>(
                    featb + (size_t)id * CC + c16 * 4);
            }
#pragma unroll
            for (int jj = 0; jj < 4; jj++) {
                int k = kk[jj];
                int pb = c16 ^ (k >> 3);       // XOR block swizzle
                *reinterpret_cast<float4*>(&s_X[wid][k][4 * pb]) = v[jj];
            }
        }
    }
    __syncwarp();

    // ---- Phase B: 8k x 8c GEMM, c-packed f32x2 (W pairs direct from LDG) ----
    // acc[j][cp]: k = 8ktg+j, channels (8ct+2cp, 8ct+2cp+1)
    ull acc[8][4];
#pragma unroll
    for (int j = 0; j < 8; j++)
#pragma unroll
        for (int cp = 0; cp < 4; cp++) acc[j][cp] = 0ull;

    const float* xw  = &s_X[wid][0][0];
    const float* wop = W_op + 8 * ct;

#pragma unroll 1
    for (int ib = 0; ib < 16; ib++) {
        const int pb = ib ^ ktg;               // this thread's physical block
        float4 x4[8];
#pragma unroll
        for (int j = 0; j < 8; j++)
            x4[j] = *reinterpret_cast<const float4*>(
                xw + (size_t)(8 * ktg + j) * XS + 4 * pb);
#pragma unroll
        for (int rr = 0; rr < 4; rr++) {
            const int row = 3 + 4 * ib + rr;
            ulonglong2 wA = __ldg(reinterpret_cast<const ulonglong2*>(
                wop + (size_t)row * COP));         // pairs (c0,c1),(c2,c3)
            ulonglong2 wB = __ldg(reinterpret_cast<const ulonglong2*>(
                wop + (size_t)row * COP + 4));     // pairs (c4,c5),(c6,c7)
#pragma unroll
            for (int j = 0; j < 8; j++) {
                ull xd = dupf(reinterpret_cast<const float*>(&x4[j])[rr]);
                ffma2p(acc[j][0], xd, wA.x);
                ffma2p(acc[j][1], xd, wA.y);
                ffma2p(acc[j][2], xd, wB.x);
                ffma2p(acc[j][3], xd, wB.y);
            }
        }
    }
    // rel tail: X cols 64+4*ktg (conflict-free over ktg), W rows 0..2
    {
        float4 x4[8];
#pragma unroll
        for (int j = 0; j < 8; j++)
            x4[j] = *reinterpret_cast<const float4*>(
                xw + (size_t)(8 * ktg + j) * XS + 64 + 4 * ktg);
#pragma unroll
        for (int rr = 0; rr < 3; rr++) {
            ulonglong2 wA = __ldg(reinterpret_cast<const ulonglong2*>(
                wop + (size_t)rr * COP));
            ulonglong2 wB = __ldg(reinterpret_cast<const ulonglong2*>(
                wop + (size_t)rr * COP + 4));
#pragma unroll
            for (int j = 0; j < 8; j++) {
                ull xd = dupf(reinterpret_cast<const float*>(&x4[j])[rr]);
                ffma2p(acc[j][0], xd, wA.x);
                ffma2p(acc[j][1], xd, wA.y);
                ffma2p(acc[j][2], xd, wB.x);
                ffma2p(acc[j][3], xd, wB.y);
            }
        }
    }

    // ---- bias + masked max over this thread's 8 k's, reduce over ktg lanes ----
    {
        float4 bA = __ldg(reinterpret_cast<const float4*>(b_op + 8 * ct));
        float4 bB = __ldg(reinterpret_cast<const float4*>(b_op + 8 * ct + 4));
        const float bv[8] = { bA.x, bA.y, bA.z, bA.w, bB.x, bB.y, bB.z, bB.w };
        float mx[8];
#pragma unroll
        for (int c = 0; c < 8; c++) mx[c] = -FLT_MAX;
#pragma unroll
        for (int j = 0; j < 8; j++) {
            if (8 * ktg + j < V) {             // whole-k masking (c-packed accs)
#pragma unroll
                for (int cp = 0; cp < 4; cp++) {
                    float2 f = *reinterpret_cast<float2*>(&acc[j][cp]);
                    mx[2 * cp]     = fmaxf(mx[2 * cp],     f.x + bv[2 * cp]);
                    mx[2 * cp + 1] = fmaxf(mx[2 * cp + 1], f.y + bv[2 * cp + 1]);
                }
            }
        }
#pragma unroll
        for (int d = 8; d < 32; d <<= 1)
#pragma unroll
            for (int c = 0; c < 8; c++)
                mx[c] = fmaxf(mx[c], __shfl_xor_sync(0xffffffffu, mx[c], d));
        float z = (V < KK) ? 0.f : -FLT_MAX;   // zero row joins iff a slot invalid
        if (ktg == 0) {                        // lanes 0..7
#pragma unroll
            for (int c = 0; c < 8; c++)
                s_pool[8 * ct + c][wid] = fmaxf(mx[c], z);
        }
    }
    __syncthreads();

    // ---- Phase C: cooperative aggregator, 4 centers share each W_agg read ----
    {
        ull acc01 = dupf(b_agg[tid]);
        ull acc23 = acc01;
#pragma unroll 8
        for (int cc = 0; cc < COP; cc++) {
            ull wd  = dupf(__ldg(&W_agg[(size_t)cc * COUT + tid]));
            ull p01 = *reinterpret_cast<const ull*>(&s_pool[cc][0]);
            ull p23 = *reinterpret_cast<const ull*>(&s_pool[cc][2]);
            ffma2p(acc01, p01, wd);
            ffma2p(acc23, p23, wd);
        }
        float2 r01 = *reinterpret_cast<float2*>(&acc01);
        float2 r23 = *reinterpret_cast<float2*>(&acc23);
        const int mbase = (blockIdx.x * WPC) & (MM - 1);
        size_t obase = ((size_t)b * MM + mbase) * COUT + tid;
        out[obase + 0 * COUT] = fmaxf(r01.x, 0.f);
        out[obase + 1 * COUT] = fmaxf(r01.y, 0.f);
        out[obase + 2 * COUT] = fmaxf(r23.x, 0.f);
        out[obase + 3 * COUT] = fmaxf(r23.y, 0.f);
    }
}

extern "C" void kernel_launch(void* const* d_in, const int* in_sizes, int n_in,
                              void* d_out, int out_size)
{
    (void)in_sizes; (void)n_in; (void)out_size;
    pointnet_sampler_kernel<<<BB * MM / WPC, 128>>>(
        (const float*)d_in[0],  // positions
        (const float*)d_in[1],  // features
        (const float*)d_in[2],  // centers
        (const float*)d_in[3],  // distances
        (const float*)d_in[4],  // W_op
        (const float*)d_in[5],  // b_op
        (const float*)d_in[6],  // W_agg
        (const float*)d_in[7],  // b_agg
        (float*)d_out);
}